// round 11
// baseline (speedup 1.0000x reference)
#include <cuda_runtime.h>
#include <cuda_bf16.h>
#include <cstdint>

// Problem constants
#define N_NODES 100000
#define N_EDGES 1600000
#define D_FEAT  256
#define UNITS   128

// Static scratch
__device__ float g_h[(size_t)N_NODES * UNITS];                    // 51.2 MB
__device__ __nv_bfloat16 g_wh[UNITS * D_FEAT];                    // w hi, [n][k]
__device__ __nv_bfloat16 g_wl[UNITS * D_FEAT];                    // w lo, [n][k]
__device__ int g_count[N_NODES];
__device__ int g_cursor[N_NODES];
__device__ int4 g_erec[N_EDGES];                                  // {dst, src, val, pad}

// ============================================================================
// Helpers
// ============================================================================
__device__ __forceinline__ uint32_t smem_u32(const void* p) {
    uint32_t a;
    asm("{ .reg .u64 t; cvta.to.shared.u64 t, %1; cvt.u32.u64 %0, t; }"
        : "=r"(a) : "l"(p));
    return a;
}

__device__ __forceinline__ uint32_t pk2(__nv_bfloat16 a, __nv_bfloat16 b) {
    uint16_t ua = *reinterpret_cast<uint16_t*>(&a);
    uint16_t ub = *reinterpret_cast<uint16_t*>(&b);
    return (uint32_t)ua | ((uint32_t)ub << 16);
}

#define LDSM_X4(r0, r1, r2, r3, addr) \
    asm volatile("ldmatrix.sync.aligned.m8n8.x4.shared.b16 {%0,%1,%2,%3}, [%4];" \
        : "=r"(r0), "=r"(r1), "=r"(r2), "=r"(r3) : "r"(addr))

#define MMA_BF16(c, a, b0, b1) \
    asm volatile("mma.sync.aligned.m16n8k16.row.col.f32.bf16.bf16.f32 " \
        "{%0,%1,%2,%3}, {%4,%5,%6,%7}, {%8,%9}, {%0,%1,%2,%3};" \
        : "+f"((c)[0]), "+f"((c)[1]), "+f"((c)[2]), "+f"((c)[3]) \
        : "r"((a)[0]), "r"((a)[1]), "r"((a)[2]), "r"((a)[3]), "r"(b0), "r"(b1))

// ============================================================================
// split_w: w[k][n] fp32 -> g_wh/g_wl[n][k] bf16 (hi/lo split), once.
// ============================================================================
__global__ __launch_bounds__(256) void split_w_kernel(const float* __restrict__ w) {
    int idx = blockIdx.x * blockDim.x + threadIdx.x;
    if (idx >= D_FEAT * UNITS) return;
    int k = idx >> 7, n = idx & 127;
    float v = w[idx];
    __nv_bfloat16 hi = __float2bfloat16(v);
    __nv_bfloat16 lo = __float2bfloat16(v - __bfloat162float(hi));
    g_wh[n * D_FEAT + k] = hi;
    g_wl[n * D_FEAT + k] = lo;
}

// ============================================================================
// GEMM (unchanged from R10): 2-way bf16 split on mma.sync, 48KB smem.
// ============================================================================
#define TILE_M  128
#define NCHUNK  16
#define PITCH   48
#define BUF_SZ  (128 * PITCH)
#define SMEM_A  0
#define SMEM_B  24576
#define SMEM_TOTAL 49152

__device__ __forceinline__ void cvt_store8(char* smem, int buf, int r, int kq,
                                           float4 v0, float4 v1) {
    float f[8] = {v0.x, v0.y, v0.z, v0.w, v1.x, v1.y, v1.z, v1.w};
    __nv_bfloat16 hi[8], lo[8];
#pragma unroll
    for (int e = 0; e < 8; e++) {
        hi[e] = __float2bfloat16(f[e]);
        lo[e] = __float2bfloat16(f[e] - __bfloat162float(hi[e]));
    }
    char* ph = smem + SMEM_A + buf * (2 * BUF_SZ) + r * PITCH + kq * 2;
    char* pl = ph + BUF_SZ;
    *(uint2*)(ph)     = make_uint2(pk2(hi[0], hi[1]), pk2(hi[2], hi[3]));
    *(uint2*)(ph + 8) = make_uint2(pk2(hi[4], hi[5]), pk2(hi[6], hi[7]));
    *(uint2*)(pl)     = make_uint2(pk2(lo[0], lo[1]), pk2(lo[2], lo[3]));
    *(uint2*)(pl + 8) = make_uint2(pk2(lo[4], lo[5]), pk2(lo[6], lo[7]));
}

__device__ __forceinline__ void b_store(char* smem, int buf, int n, int kq,
                                        uint4 bh, uint4 bl) {
    char* ph = smem + SMEM_B + buf * (2 * BUF_SZ) + n * PITCH + kq * 2;
    *(uint4*)(ph)          = bh;
    *(uint4*)(ph + BUF_SZ) = bl;
}

__global__ __launch_bounds__(256) void gemm_mma_kernel(const float* __restrict__ x,
                                                       float* __restrict__ h) {
    extern __shared__ char smem[];
    const uint32_t sb = smem_u32(smem);
    const int tid  = threadIdx.x;
    const int wid  = tid >> 5;
    const int lane = tid & 31;
    const int block_row = blockIdx.x * TILE_M;

    const int wm = (wid & 3) * 32;
    const int wn = (wid >> 2) * 64;

    const int pr = tid >> 1;
    const int pk = (tid & 1) * 8;
    const int grow = block_row + pr;
    const bool prow_ok = grow < N_NODES;
    const float* xrow = x + (size_t)(prow_ok ? grow : 0) * D_FEAT;
    const __nv_bfloat16* whrow = g_wh + pr * D_FEAT + pk;
    const __nv_bfloat16* wlrow = g_wl + pr * D_FEAT + pk;

    {
        float4 v0 = make_float4(0, 0, 0, 0), v1 = v0;
        if (prow_ok) {
            v0 = *(const float4*)(xrow + pk);
            v1 = *(const float4*)(xrow + pk + 4);
        }
        cvt_store8(smem, 0, pr, pk, v0, v1);
        uint4 bh = *(const uint4*)(whrow);
        uint4 bl = *(const uint4*)(wlrow);
        b_store(smem, 0, pr, pk, bh, bl);
    }
    __syncthreads();

    float acc[2][8][4];
#pragma unroll
    for (int i = 0; i < 2; i++)
#pragma unroll
        for (int j = 0; j < 8; j++)
#pragma unroll
            for (int q = 0; q < 4; q++) acc[i][j][q] = 0.0f;

    const uint32_t aRow = (uint32_t)(wm + (lane & 15)) * PITCH + ((lane >> 4) << 4);
    const uint32_t bRow = (uint32_t)(wn + (lane & 7) + ((lane >> 4) << 3)) * PITCH
                          + (((lane >> 3) & 1) << 4);

    for (int c = 0; c < NCHUNK; c++) {
        float4 v0 = make_float4(0, 0, 0, 0), v1 = v0;
        uint4 nbh = make_uint4(0, 0, 0, 0), nbl = nbh;
        const bool pf = (c + 1 < NCHUNK);
        if (pf) {
            if (prow_ok) {
                v0 = *(const float4*)(xrow + (c + 1) * 16 + pk);
                v1 = *(const float4*)(xrow + (c + 1) * 16 + pk + 4);
            }
            nbh = *(const uint4*)(whrow + (c + 1) * 16);
            nbl = *(const uint4*)(wlrow + (c + 1) * 16);
        }

        const uint32_t abase = sb + SMEM_A + (c & 1) * (2 * BUF_SZ) + aRow;
        uint32_t ah[2][4], al[2][4];
#pragma unroll
        for (int i = 0; i < 2; i++) {
            LDSM_X4(ah[i][0], ah[i][1], ah[i][2], ah[i][3], abase + i * 16 * PITCH);
            LDSM_X4(al[i][0], al[i][1], al[i][2], al[i][3],
                    abase + i * 16 * PITCH + BUF_SZ);
        }

        const uint32_t bbH = sb + SMEM_B + (c & 1) * (2 * BUF_SZ) + bRow;
        const uint32_t bbL = bbH + BUF_SZ;
#pragma unroll
        for (int jp = 0; jp < 4; jp++) {
            uint32_t bh[4], bl[4];
            LDSM_X4(bh[0], bh[1], bh[2], bh[3], bbH + jp * 16 * PITCH);
            LDSM_X4(bl[0], bl[1], bl[2], bl[3], bbL + jp * 16 * PITCH);
#pragma unroll
            for (int i = 0; i < 2; i++) {
                MMA_BF16(acc[i][2 * jp],     ah[i], bh[0], bh[1]);
                MMA_BF16(acc[i][2 * jp + 1], ah[i], bh[2], bh[3]);
                MMA_BF16(acc[i][2 * jp],     ah[i], bl[0], bl[1]);
                MMA_BF16(acc[i][2 * jp + 1], ah[i], bl[2], bl[3]);
                MMA_BF16(acc[i][2 * jp],     al[i], bh[0], bh[1]);
                MMA_BF16(acc[i][2 * jp + 1], al[i], bh[2], bh[3]);
            }
        }

        if (pf) {
            cvt_store8(smem, (c + 1) & 1, pr, pk, v0, v1);
            b_store(smem, (c + 1) & 1, pr, pk, nbh, nbl);
        }
        __syncthreads();
    }

#pragma unroll
    for (int i = 0; i < 2; i++) {
#pragma unroll
        for (int j = 0; j < 8; j++) {
            int row0 = block_row + wm + i * 16 + (lane >> 2);
            int col  = wn + j * 8 + (lane & 3) * 2;
            if (row0 < N_NODES)
                *(float2*)(h + (size_t)row0 * UNITS + col) =
                    make_float2(acc[i][j][0], acc[i][j][1]);
            int row1 = row0 + 8;
            if (row1 < N_NODES)
                *(float2*)(h + (size_t)row1 * UNITS + col) =
                    make_float2(acc[i][j][2], acc[i][j][3]);
        }
    }
}

// ============================================================================
// CSR-by-dst build: histogram -> scan -> bin (16B records)
// ============================================================================
__global__ __launch_bounds__(256) void hist_kernel(const int* __restrict__ dst) {
    int i = blockIdx.x * blockDim.x + threadIdx.x;
    if (i < N_EDGES) atomicAdd(&g_count[dst[i]], 1);
}

__global__ __launch_bounds__(1024) void scan_kernel() {
    __shared__ int part[1024];
    const int tid = threadIdx.x;
    const int CHUNK = (N_NODES + 1023) / 1024;   // 98
    int begin = tid * CHUNK;
    int end = begin + CHUNK;
    if (end > N_NODES) end = N_NODES;
    if (begin > N_NODES) begin = N_NODES;

    int s = 0;
    for (int i = begin; i < end; i++) s += g_count[i];
    part[tid] = s;
    __syncthreads();

    for (int off = 1; off < 1024; off <<= 1) {
        int v = (tid >= off) ? part[tid - off] : 0;
        __syncthreads();
        part[tid] += v;
        __syncthreads();
    }

    int run = (tid == 0) ? 0 : part[tid - 1];
    for (int i = begin; i < end; i++) {
        g_cursor[i] = run;
        run += g_count[i];
    }
}

__global__ __launch_bounds__(256) void bin_kernel(const int* __restrict__ src,
                                                  const int* __restrict__ dst,
                                                  const float* __restrict__ vals) {
    int i = blockIdx.x * blockDim.x + threadIdx.x;
    if (i >= N_EDGES) return;
    int d = dst[i];
    int pos = atomicAdd(&g_cursor[d], 1);
    g_erec[pos] = make_int4(d, src[i], __float_as_int(vals[i]), 0);
}

// ============================================================================
// Aggregate: flat segmented reduction over dst-sorted edges.
// Each warp owns EPW consecutive edges; register accumulate; atomic flush
// only at dst boundaries (~2 per warp on average).
// ============================================================================
#define EPW 16

__global__ __launch_bounds__(256) void aggregate_kernel(const float* __restrict__ h,
                                                        float* __restrict__ out) {
    const int warp = (blockIdx.x * blockDim.x + threadIdx.x) >> 5;
    const int lane = threadIdx.x & 31;
    const int base = warp * EPW;
    if (base >= N_EDGES) return;

    const int4* ep = g_erec + base;

    // Stage all 16 records up front (broadcast loads; enables batched gathers)
    int4 r[EPW];
#pragma unroll
    for (int i = 0; i < EPW; i++) r[i] = __ldg(ep + i);

    float4 acc = make_float4(0.f, 0.f, 0.f, 0.f);
    int cur = r[0].x;

#pragma unroll
    for (int i = 0; i < EPW; i++) {
        const int d = r[i].x;
        const int s = r[i].y;
        const float v = __int_as_float(r[i].z);
        if (d != cur) {
            atomicAdd((float4*)(out + (size_t)cur * UNITS + lane * 4), acc);
            acc = make_float4(0.f, 0.f, 0.f, 0.f);
            cur = d;
        }
        const float4 hv = *(const float4*)(h + (size_t)s * UNITS + lane * 4);
        acc.x += v * hv.x;
        acc.y += v * hv.y;
        acc.z += v * hv.z;
        acc.w += v * hv.w;
    }
    atomicAdd((float4*)(out + (size_t)cur * UNITS + lane * 4), acc);
}

// ============================================================================
// Launch
// ============================================================================
extern "C" void kernel_launch(void* const* d_in, const int* in_sizes, int n_in,
                              void* d_out, int out_size) {
    const float* x    = (const float*)d_in[0];
    const float* w    = (const float*)d_in[1];
    const int*   src  = (const int*)d_in[2];
    const int*   dst  = (const int*)d_in[3];
    const float* vals = (const float*)d_in[4];
    float* out = (float*)d_out;

    cudaMemsetAsync(d_out, 0, (size_t)out_size * sizeof(float), 0);

    float* h;
    cudaGetSymbolAddress((void**)&h, g_h);
    int* countp;
    cudaGetSymbolAddress((void**)&countp, g_count);
    cudaMemsetAsync(countp, 0, N_NODES * sizeof(int), 0);

    // CSR build (independent of GEMM)
    hist_kernel<<<(N_EDGES + 255) / 256, 256>>>(dst);
    scan_kernel<<<1, 1024>>>();
    bin_kernel<<<(N_EDGES + 255) / 256, 256>>>(src, dst, vals);

    // w split + GEMM
    split_w_kernel<<<(D_FEAT * UNITS + 255) / 256, 256>>>(w);
    cudaFuncSetAttribute(gemm_mma_kernel,
                         cudaFuncAttributeMaxDynamicSharedMemorySize, SMEM_TOTAL);
    int gemm_blocks = (N_NODES + TILE_M - 1) / TILE_M;
    gemm_mma_kernel<<<gemm_blocks, 256, SMEM_TOTAL>>>(x, h);

    // Balanced segmented aggregate
    int nwarps = (N_EDGES + EPW - 1) / EPW;             // 100000
    int agg_blocks = (nwarps * 32 + 255) / 256;
    aggregate_kernel<<<agg_blocks, 256>>>(h, out);
}

// round 12
// speedup vs baseline: 1.0542x; 1.0542x over previous
#include <cuda_runtime.h>
#include <cuda_bf16.h>
#include <cstdint>

// Problem constants
#define N_NODES 100000
#define N_EDGES 1600000
#define D_FEAT  256
#define UNITS   128

// Static scratch
__device__ float g_h[(size_t)N_NODES * UNITS];                    // 51.2 MB
__device__ __nv_bfloat16 g_wh[UNITS * D_FEAT];                    // w hi, [n][k]
__device__ __nv_bfloat16 g_wl[UNITS * D_FEAT];                    // w lo, [n][k]
__device__ int g_count[N_NODES];
__device__ int g_cursor[N_NODES];
__device__ int4 g_erec[N_EDGES];                                  // {dst, src, val, pad}

// ============================================================================
// Helpers
// ============================================================================
__device__ __forceinline__ uint32_t smem_u32(const void* p) {
    uint32_t a;
    asm("{ .reg .u64 t; cvta.to.shared.u64 t, %1; cvt.u32.u64 %0, t; }"
        : "=r"(a) : "l"(p));
    return a;
}

__device__ __forceinline__ uint32_t pk2(__nv_bfloat16 a, __nv_bfloat16 b) {
    uint16_t ua = *reinterpret_cast<uint16_t*>(&a);
    uint16_t ub = *reinterpret_cast<uint16_t*>(&b);
    return (uint32_t)ua | ((uint32_t)ub << 16);
}

#define LDSM_X4(r0, r1, r2, r3, addr) \
    asm volatile("ldmatrix.sync.aligned.m8n8.x4.shared.b16 {%0,%1,%2,%3}, [%4];" \
        : "=r"(r0), "=r"(r1), "=r"(r2), "=r"(r3) : "r"(addr))

#define MMA_BF16(c, a, b0, b1) \
    asm volatile("mma.sync.aligned.m16n8k16.row.col.f32.bf16.bf16.f32 " \
        "{%0,%1,%2,%3}, {%4,%5,%6,%7}, {%8,%9}, {%0,%1,%2,%3};" \
        : "+f"((c)[0]), "+f"((c)[1]), "+f"((c)[2]), "+f"((c)[3]) \
        : "r"((a)[0]), "r"((a)[1]), "r"((a)[2]), "r"((a)[3]), "r"(b0), "r"(b1))

// ============================================================================
// split_w: w[k][n] fp32 -> g_wh/g_wl[n][k] bf16 (hi/lo split), once.
// ============================================================================
__global__ __launch_bounds__(256) void split_w_kernel(const float* __restrict__ w) {
    int idx = blockIdx.x * blockDim.x + threadIdx.x;
    if (idx >= D_FEAT * UNITS) return;
    int k = idx >> 7, n = idx & 127;
    float v = w[idx];
    __nv_bfloat16 hi = __float2bfloat16(v);
    __nv_bfloat16 lo = __float2bfloat16(v - __bfloat162float(hi));
    g_wh[n * D_FEAT + k] = hi;
    g_wl[n * D_FEAT + k] = lo;
}

// ============================================================================
// GEMM (unchanged from R10): 2-way bf16 split on mma.sync, 48KB smem.
// ============================================================================
#define TILE_M  128
#define NCHUNK  16
#define PITCH   48
#define BUF_SZ  (128 * PITCH)
#define SMEM_A  0
#define SMEM_B  24576
#define SMEM_TOTAL 49152

__device__ __forceinline__ void cvt_store8(char* smem, int buf, int r, int kq,
                                           float4 v0, float4 v1) {
    float f[8] = {v0.x, v0.y, v0.z, v0.w, v1.x, v1.y, v1.z, v1.w};
    __nv_bfloat16 hi[8], lo[8];
#pragma unroll
    for (int e = 0; e < 8; e++) {
        hi[e] = __float2bfloat16(f[e]);
        lo[e] = __float2bfloat16(f[e] - __bfloat162float(hi[e]));
    }
    char* ph = smem + SMEM_A + buf * (2 * BUF_SZ) + r * PITCH + kq * 2;
    char* pl = ph + BUF_SZ;
    *(uint2*)(ph)     = make_uint2(pk2(hi[0], hi[1]), pk2(hi[2], hi[3]));
    *(uint2*)(ph + 8) = make_uint2(pk2(hi[4], hi[5]), pk2(hi[6], hi[7]));
    *(uint2*)(pl)     = make_uint2(pk2(lo[0], lo[1]), pk2(lo[2], lo[3]));
    *(uint2*)(pl + 8) = make_uint2(pk2(lo[4], lo[5]), pk2(lo[6], lo[7]));
}

__device__ __forceinline__ void b_store(char* smem, int buf, int n, int kq,
                                        uint4 bh, uint4 bl) {
    char* ph = smem + SMEM_B + buf * (2 * BUF_SZ) + n * PITCH + kq * 2;
    *(uint4*)(ph)          = bh;
    *(uint4*)(ph + BUF_SZ) = bl;
}

__global__ __launch_bounds__(256) void gemm_mma_kernel(const float* __restrict__ x,
                                                       float* __restrict__ h) {
    extern __shared__ char smem[];
    const uint32_t sb = smem_u32(smem);
    const int tid  = threadIdx.x;
    const int wid  = tid >> 5;
    const int lane = tid & 31;
    const int block_row = blockIdx.x * TILE_M;

    const int wm = (wid & 3) * 32;
    const int wn = (wid >> 2) * 64;

    const int pr = tid >> 1;
    const int pk = (tid & 1) * 8;
    const int grow = block_row + pr;
    const bool prow_ok = grow < N_NODES;
    const float* xrow = x + (size_t)(prow_ok ? grow : 0) * D_FEAT;
    const __nv_bfloat16* whrow = g_wh + pr * D_FEAT + pk;
    const __nv_bfloat16* wlrow = g_wl + pr * D_FEAT + pk;

    {
        float4 v0 = make_float4(0, 0, 0, 0), v1 = v0;
        if (prow_ok) {
            v0 = *(const float4*)(xrow + pk);
            v1 = *(const float4*)(xrow + pk + 4);
        }
        cvt_store8(smem, 0, pr, pk, v0, v1);
        uint4 bh = *(const uint4*)(whrow);
        uint4 bl = *(const uint4*)(wlrow);
        b_store(smem, 0, pr, pk, bh, bl);
    }
    __syncthreads();

    float acc[2][8][4];
#pragma unroll
    for (int i = 0; i < 2; i++)
#pragma unroll
        for (int j = 0; j < 8; j++)
#pragma unroll
            for (int q = 0; q < 4; q++) acc[i][j][q] = 0.0f;

    const uint32_t aRow = (uint32_t)(wm + (lane & 15)) * PITCH + ((lane >> 4) << 4);
    const uint32_t bRow = (uint32_t)(wn + (lane & 7) + ((lane >> 4) << 3)) * PITCH
                          + (((lane >> 3) & 1) << 4);

    for (int c = 0; c < NCHUNK; c++) {
        float4 v0 = make_float4(0, 0, 0, 0), v1 = v0;
        uint4 nbh = make_uint4(0, 0, 0, 0), nbl = nbh;
        const bool pf = (c + 1 < NCHUNK);
        if (pf) {
            if (prow_ok) {
                v0 = *(const float4*)(xrow + (c + 1) * 16 + pk);
                v1 = *(const float4*)(xrow + (c + 1) * 16 + pk + 4);
            }
            nbh = *(const uint4*)(whrow + (c + 1) * 16);
            nbl = *(const uint4*)(wlrow + (c + 1) * 16);
        }

        const uint32_t abase = sb + SMEM_A + (c & 1) * (2 * BUF_SZ) + aRow;
        uint32_t ah[2][4], al[2][4];
#pragma unroll
        for (int i = 0; i < 2; i++) {
            LDSM_X4(ah[i][0], ah[i][1], ah[i][2], ah[i][3], abase + i * 16 * PITCH);
            LDSM_X4(al[i][0], al[i][1], al[i][2], al[i][3],
                    abase + i * 16 * PITCH + BUF_SZ);
        }

        const uint32_t bbH = sb + SMEM_B + (c & 1) * (2 * BUF_SZ) + bRow;
        const uint32_t bbL = bbH + BUF_SZ;
#pragma unroll
        for (int jp = 0; jp < 4; jp++) {
            uint32_t bh[4], bl[4];
            LDSM_X4(bh[0], bh[1], bh[2], bh[3], bbH + jp * 16 * PITCH);
            LDSM_X4(bl[0], bl[1], bl[2], bl[3], bbL + jp * 16 * PITCH);
#pragma unroll
            for (int i = 0; i < 2; i++) {
                MMA_BF16(acc[i][2 * jp],     ah[i], bh[0], bh[1]);
                MMA_BF16(acc[i][2 * jp + 1], ah[i], bh[2], bh[3]);
                MMA_BF16(acc[i][2 * jp],     ah[i], bl[0], bl[1]);
                MMA_BF16(acc[i][2 * jp + 1], ah[i], bl[2], bl[3]);
                MMA_BF16(acc[i][2 * jp],     al[i], bh[0], bh[1]);
                MMA_BF16(acc[i][2 * jp + 1], al[i], bh[2], bh[3]);
            }
        }

        if (pf) {
            cvt_store8(smem, (c + 1) & 1, pr, pk, v0, v1);
            b_store(smem, (c + 1) & 1, pr, pk, nbh, nbl);
        }
        __syncthreads();
    }

#pragma unroll
    for (int i = 0; i < 2; i++) {
#pragma unroll
        for (int j = 0; j < 8; j++) {
            int row0 = block_row + wm + i * 16 + (lane >> 2);
            int col  = wn + j * 8 + (lane & 3) * 2;
            if (row0 < N_NODES)
                *(float2*)(h + (size_t)row0 * UNITS + col) =
                    make_float2(acc[i][j][0], acc[i][j][1]);
            int row1 = row0 + 8;
            if (row1 < N_NODES)
                *(float2*)(h + (size_t)row1 * UNITS + col) =
                    make_float2(acc[i][j][2], acc[i][j][3]);
        }
    }
}

// ============================================================================
// CSR-by-dst build: histogram -> scan -> bin (16B records)
// ============================================================================
__global__ __launch_bounds__(256) void hist_kernel(const int* __restrict__ dst) {
    int i = blockIdx.x * blockDim.x + threadIdx.x;
    if (i < N_EDGES) atomicAdd(&g_count[dst[i]], 1);
}

__global__ __launch_bounds__(1024) void scan_kernel() {
    __shared__ int part[1024];
    const int tid = threadIdx.x;
    const int CHUNK = (N_NODES + 1023) / 1024;   // 98
    int begin = tid * CHUNK;
    int end = begin + CHUNK;
    if (end > N_NODES) end = N_NODES;
    if (begin > N_NODES) begin = N_NODES;

    int s = 0;
    for (int i = begin; i < end; i++) s += g_count[i];
    part[tid] = s;
    __syncthreads();

    for (int off = 1; off < 1024; off <<= 1) {
        int v = (tid >= off) ? part[tid - off] : 0;
        __syncthreads();
        part[tid] += v;
        __syncthreads();
    }

    int run = (tid == 0) ? 0 : part[tid - 1];
    for (int i = begin; i < end; i++) {
        g_cursor[i] = run;
        run += g_count[i];
    }
}

__global__ __launch_bounds__(256) void bin_kernel(const int* __restrict__ src,
                                                  const int* __restrict__ dst,
                                                  const float* __restrict__ vals) {
    int i = blockIdx.x * blockDim.x + threadIdx.x;
    if (i >= N_EDGES) return;
    int d = dst[i];
    int pos = atomicAdd(&g_cursor[d], 1);
    g_erec[pos] = make_int4(d, src[i], __float_as_int(vals[i]), 0);
}

// ============================================================================
// Aggregate: flat segmented reduction, STRICT phase separation:
//   (1) load records  (2) all gathers, no stores between  (3) scale  (4) merge
// EPW=8 edges/warp -> ~80 regs, 8-deep gather MLP per warp, 200K warps.
// ============================================================================
#define EPW 8

__global__ __launch_bounds__(256, 2) void aggregate_kernel(const float* __restrict__ h,
                                                           float* __restrict__ out) {
    const int warp = (blockIdx.x * blockDim.x + threadIdx.x) >> 5;
    const int lane = threadIdx.x & 31;
    const int base = warp * EPW;
    if (base >= N_EDGES) return;

    const int4* ep = g_erec + base;

    // Phase 1: edge records (uniform across warp; consecutive 16B loads)
    int4 r[EPW];
#pragma unroll
    for (int i = 0; i < EPW; i++) r[i] = __ldg(ep + i);

    // Phase 2: all gathers issued back-to-back (independent -> full MLP)
    float4 g[EPW];
#pragma unroll
    for (int i = 0; i < EPW; i++)
        g[i] = *(const float4*)(h + (size_t)r[i].y * UNITS + lane * 4);

    // Phase 3: scale by edge value (register-only)
#pragma unroll
    for (int i = 0; i < EPW; i++) {
        const float v = __int_as_float(r[i].z);
        g[i].x *= v; g[i].y *= v; g[i].z *= v; g[i].w *= v;
    }

    // Phase 4: merge runs of equal dst; atomic flush at boundaries only
    float4 acc = g[0];
    int cur = r[0].x;
#pragma unroll
    for (int i = 1; i < EPW; i++) {
        if (r[i].x != cur) {
            atomicAdd((float4*)(out + (size_t)cur * UNITS + lane * 4), acc);
            acc = g[i];
            cur = r[i].x;
        } else {
            acc.x += g[i].x; acc.y += g[i].y; acc.z += g[i].z; acc.w += g[i].w;
        }
    }
    atomicAdd((float4*)(out + (size_t)cur * UNITS + lane * 4), acc);
}

// ============================================================================
// Launch
// ============================================================================
extern "C" void kernel_launch(void* const* d_in, const int* in_sizes, int n_in,
                              void* d_out, int out_size) {
    const float* x    = (const float*)d_in[0];
    const float* w    = (const float*)d_in[1];
    const int*   src  = (const int*)d_in[2];
    const int*   dst  = (const int*)d_in[3];
    const float* vals = (const float*)d_in[4];
    float* out = (float*)d_out;

    cudaMemsetAsync(d_out, 0, (size_t)out_size * sizeof(float), 0);

    float* h;
    cudaGetSymbolAddress((void**)&h, g_h);
    int* countp;
    cudaGetSymbolAddress((void**)&countp, g_count);
    cudaMemsetAsync(countp, 0, N_NODES * sizeof(int), 0);

    // CSR-by-dst build
    hist_kernel<<<(N_EDGES + 255) / 256, 256>>>(dst);
    scan_kernel<<<1, 1024>>>();
    bin_kernel<<<(N_EDGES + 255) / 256, 256>>>(src, dst, vals);

    // w split + GEMM
    split_w_kernel<<<(D_FEAT * UNITS + 255) / 256, 256>>>(w);
    cudaFuncSetAttribute(gemm_mma_kernel,
                         cudaFuncAttributeMaxDynamicSharedMemorySize, SMEM_TOTAL);
    int gemm_blocks = (N_NODES + TILE_M - 1) / TILE_M;
    gemm_mma_kernel<<<gemm_blocks, 256, SMEM_TOTAL>>>(x, h);

    // Balanced segmented aggregate
    int nwarps = (N_EDGES + EPW - 1) / EPW;             // 200000
    int agg_blocks = (nwarps * 32 + 255) / 256;
    aggregate_kernel<<<agg_blocks, 256>>>(h, out);
}

// round 13
// speedup vs baseline: 1.0720x; 1.0169x over previous
#include <cuda_runtime.h>
#include <cuda_bf16.h>
#include <cstdint>

// Problem constants
#define N_NODES 100000
#define N_EDGES 1600000
#define D_FEAT  256
#define UNITS   128

// Static scratch
__device__ float g_h[(size_t)N_NODES * UNITS];                    // 51.2 MB
__device__ __nv_bfloat16 g_wh[UNITS * D_FEAT];                    // w hi, [n][k]
__device__ __nv_bfloat16 g_wl[UNITS * D_FEAT];                    // w lo, [n][k]
__device__ int g_count[N_NODES];
__device__ int g_cursor[N_NODES];
__device__ int4 g_erec[N_EDGES];                                  // {dst, src, val, pad}

// ============================================================================
// Helpers
// ============================================================================
__device__ __forceinline__ uint32_t smem_u32(const void* p) {
    uint32_t a;
    asm("{ .reg .u64 t; cvta.to.shared.u64 t, %1; cvt.u32.u64 %0, t; }"
        : "=r"(a) : "l"(p));
    return a;
}

__device__ __forceinline__ uint32_t pk2(__nv_bfloat16 a, __nv_bfloat16 b) {
    uint16_t ua = *reinterpret_cast<uint16_t*>(&a);
    uint16_t ub = *reinterpret_cast<uint16_t*>(&b);
    return (uint32_t)ua | ((uint32_t)ub << 16);
}

#define LDSM_X4(r0, r1, r2, r3, addr) \
    asm volatile("ldmatrix.sync.aligned.m8n8.x4.shared.b16 {%0,%1,%2,%3}, [%4];" \
        : "=r"(r0), "=r"(r1), "=r"(r2), "=r"(r3) : "r"(addr))

#define MMA_BF16(c, a, b0, b1) \
    asm volatile("mma.sync.aligned.m16n8k16.row.col.f32.bf16.bf16.f32 " \
        "{%0,%1,%2,%3}, {%4,%5,%6,%7}, {%8,%9}, {%0,%1,%2,%3};" \
        : "+f"((c)[0]), "+f"((c)[1]), "+f"((c)[2]), "+f"((c)[3]) \
        : "r"((a)[0]), "r"((a)[1]), "r"((a)[2]), "r"((a)[3]), "r"(b0), "r"(b1))

// ============================================================================
// split_w
// ============================================================================
__global__ __launch_bounds__(256) void split_w_kernel(const float* __restrict__ w) {
    int idx = blockIdx.x * blockDim.x + threadIdx.x;
    if (idx >= D_FEAT * UNITS) return;
    int k = idx >> 7, n = idx & 127;
    float v = w[idx];
    __nv_bfloat16 hi = __float2bfloat16(v);
    __nv_bfloat16 lo = __float2bfloat16(v - __bfloat162float(hi));
    g_wh[n * D_FEAT + k] = hi;
    g_wl[n * D_FEAT + k] = lo;
}

// ============================================================================
// GEMM (unchanged from R10): 2-way bf16 split on mma.sync, 48KB smem.
// ============================================================================
#define TILE_M  128
#define NCHUNK  16
#define PITCH   48
#define BUF_SZ  (128 * PITCH)
#define SMEM_A  0
#define SMEM_B  24576
#define SMEM_TOTAL 49152

__device__ __forceinline__ void cvt_store8(char* smem, int buf, int r, int kq,
                                           float4 v0, float4 v1) {
    float f[8] = {v0.x, v0.y, v0.z, v0.w, v1.x, v1.y, v1.z, v1.w};
    __nv_bfloat16 hi[8], lo[8];
#pragma unroll
    for (int e = 0; e < 8; e++) {
        hi[e] = __float2bfloat16(f[e]);
        lo[e] = __float2bfloat16(f[e] - __bfloat162float(hi[e]));
    }
    char* ph = smem + SMEM_A + buf * (2 * BUF_SZ) + r * PITCH + kq * 2;
    char* pl = ph + BUF_SZ;
    *(uint2*)(ph)     = make_uint2(pk2(hi[0], hi[1]), pk2(hi[2], hi[3]));
    *(uint2*)(ph + 8) = make_uint2(pk2(hi[4], hi[5]), pk2(hi[6], hi[7]));
    *(uint2*)(pl)     = make_uint2(pk2(lo[0], lo[1]), pk2(lo[2], lo[3]));
    *(uint2*)(pl + 8) = make_uint2(pk2(lo[4], lo[5]), pk2(lo[6], lo[7]));
}

__device__ __forceinline__ void b_store(char* smem, int buf, int n, int kq,
                                        uint4 bh, uint4 bl) {
    char* ph = smem + SMEM_B + buf * (2 * BUF_SZ) + n * PITCH + kq * 2;
    *(uint4*)(ph)          = bh;
    *(uint4*)(ph + BUF_SZ) = bl;
}

__global__ __launch_bounds__(256) void gemm_mma_kernel(const float* __restrict__ x,
                                                       float* __restrict__ h) {
    extern __shared__ char smem[];
    const uint32_t sb = smem_u32(smem);
    const int tid  = threadIdx.x;
    const int wid  = tid >> 5;
    const int lane = tid & 31;
    const int block_row = blockIdx.x * TILE_M;

    const int wm = (wid & 3) * 32;
    const int wn = (wid >> 2) * 64;

    const int pr = tid >> 1;
    const int pk = (tid & 1) * 8;
    const int grow = block_row + pr;
    const bool prow_ok = grow < N_NODES;
    const float* xrow = x + (size_t)(prow_ok ? grow : 0) * D_FEAT;
    const __nv_bfloat16* whrow = g_wh + pr * D_FEAT + pk;
    const __nv_bfloat16* wlrow = g_wl + pr * D_FEAT + pk;

    {
        float4 v0 = make_float4(0, 0, 0, 0), v1 = v0;
        if (prow_ok) {
            v0 = *(const float4*)(xrow + pk);
            v1 = *(const float4*)(xrow + pk + 4);
        }
        cvt_store8(smem, 0, pr, pk, v0, v1);
        uint4 bh = *(const uint4*)(whrow);
        uint4 bl = *(const uint4*)(wlrow);
        b_store(smem, 0, pr, pk, bh, bl);
    }
    __syncthreads();

    float acc[2][8][4];
#pragma unroll
    for (int i = 0; i < 2; i++)
#pragma unroll
        for (int j = 0; j < 8; j++)
#pragma unroll
            for (int q = 0; q < 4; q++) acc[i][j][q] = 0.0f;

    const uint32_t aRow = (uint32_t)(wm + (lane & 15)) * PITCH + ((lane >> 4) << 4);
    const uint32_t bRow = (uint32_t)(wn + (lane & 7) + ((lane >> 4) << 3)) * PITCH
                          + (((lane >> 3) & 1) << 4);

    for (int c = 0; c < NCHUNK; c++) {
        float4 v0 = make_float4(0, 0, 0, 0), v1 = v0;
        uint4 nbh = make_uint4(0, 0, 0, 0), nbl = nbh;
        const bool pf = (c + 1 < NCHUNK);
        if (pf) {
            if (prow_ok) {
                v0 = *(const float4*)(xrow + (c + 1) * 16 + pk);
                v1 = *(const float4*)(xrow + (c + 1) * 16 + pk + 4);
            }
            nbh = *(const uint4*)(whrow + (c + 1) * 16);
            nbl = *(const uint4*)(wlrow + (c + 1) * 16);
        }

        const uint32_t abase = sb + SMEM_A + (c & 1) * (2 * BUF_SZ) + aRow;
        uint32_t ah[2][4], al[2][4];
#pragma unroll
        for (int i = 0; i < 2; i++) {
            LDSM_X4(ah[i][0], ah[i][1], ah[i][2], ah[i][3], abase + i * 16 * PITCH);
            LDSM_X4(al[i][0], al[i][1], al[i][2], al[i][3],
                    abase + i * 16 * PITCH + BUF_SZ);
        }

        const uint32_t bbH = sb + SMEM_B + (c & 1) * (2 * BUF_SZ) + bRow;
        const uint32_t bbL = bbH + BUF_SZ;
#pragma unroll
        for (int jp = 0; jp < 4; jp++) {
            uint32_t bh[4], bl[4];
            LDSM_X4(bh[0], bh[1], bh[2], bh[3], bbH + jp * 16 * PITCH);
            LDSM_X4(bl[0], bl[1], bl[2], bl[3], bbL + jp * 16 * PITCH);
#pragma unroll
            for (int i = 0; i < 2; i++) {
                MMA_BF16(acc[i][2 * jp],     ah[i], bh[0], bh[1]);
                MMA_BF16(acc[i][2 * jp + 1], ah[i], bh[2], bh[3]);
                MMA_BF16(acc[i][2 * jp],     ah[i], bl[0], bl[1]);
                MMA_BF16(acc[i][2 * jp + 1], ah[i], bl[2], bl[3]);
                MMA_BF16(acc[i][2 * jp],     al[i], bh[0], bh[1]);
                MMA_BF16(acc[i][2 * jp + 1], al[i], bh[2], bh[3]);
            }
        }

        if (pf) {
            cvt_store8(smem, (c + 1) & 1, pr, pk, v0, v1);
            b_store(smem, (c + 1) & 1, pr, pk, nbh, nbl);
        }
        __syncthreads();
    }

#pragma unroll
    for (int i = 0; i < 2; i++) {
#pragma unroll
        for (int j = 0; j < 8; j++) {
            int row0 = block_row + wm + i * 16 + (lane >> 2);
            int col  = wn + j * 8 + (lane & 3) * 2;
            if (row0 < N_NODES)
                *(float2*)(h + (size_t)row0 * UNITS + col) =
                    make_float2(acc[i][j][0], acc[i][j][1]);
            int row1 = row0 + 8;
            if (row1 < N_NODES)
                *(float2*)(h + (size_t)row1 * UNITS + col) =
                    make_float2(acc[i][j][2], acc[i][j][3]);
        }
    }
}

// ============================================================================
// CSR-by-dst build: histogram -> scan -> bin (16B records)
// ============================================================================
__global__ __launch_bounds__(256) void hist_kernel(const int* __restrict__ dst) {
    int i = blockIdx.x * blockDim.x + threadIdx.x;
    if (i < N_EDGES) atomicAdd(&g_count[dst[i]], 1);
}

__global__ __launch_bounds__(1024) void scan_kernel() {
    __shared__ int part[1024];
    const int tid = threadIdx.x;
    const int CHUNK = (N_NODES + 1023) / 1024;   // 98
    int begin = tid * CHUNK;
    int end = begin + CHUNK;
    if (end > N_NODES) end = N_NODES;
    if (begin > N_NODES) begin = N_NODES;

    int s = 0;
    for (int i = begin; i < end; i++) s += g_count[i];
    part[tid] = s;
    __syncthreads();

    for (int off = 1; off < 1024; off <<= 1) {
        int v = (tid >= off) ? part[tid - off] : 0;
        __syncthreads();
        part[tid] += v;
        __syncthreads();
    }

    int run = (tid == 0) ? 0 : part[tid - 1];
    for (int i = begin; i < end; i++) {
        g_cursor[i] = run;
        run += g_count[i];
    }
}

__global__ __launch_bounds__(256) void bin_kernel(const int* __restrict__ src,
                                                  const int* __restrict__ dst,
                                                  const float* __restrict__ vals) {
    int i = blockIdx.x * blockDim.x + threadIdx.x;
    if (i >= N_EDGES) return;
    int d = dst[i];
    int pos = atomicAdd(&g_cursor[d], 1);
    g_erec[pos] = make_int4(d, src[i], __float_as_int(vals[i]), 0);
}

// ============================================================================
// Aggregate: flat segmented reduction, strict phase separation.
// EPW=4 -> ~48 regs -> 5 CTAs/SM (40 warps, ~62% occ). 400K warps.
// ============================================================================
#define EPW 4

__global__ __launch_bounds__(256) void aggregate_kernel(const float* __restrict__ h,
                                                        float* __restrict__ out) {
    const int warp = (blockIdx.x * blockDim.x + threadIdx.x) >> 5;
    const int lane = threadIdx.x & 31;
    const int base = warp * EPW;
    if (base >= N_EDGES) return;

    const int4* ep = g_erec + base;

    // Phase 1: edge records (broadcast loads)
    int4 r[EPW];
#pragma unroll
    for (int i = 0; i < EPW; i++) r[i] = __ldg(ep + i);

    // Phase 2: all gathers back-to-back (independent -> full MLP)
    float4 g[EPW];
#pragma unroll
    for (int i = 0; i < EPW; i++)
        g[i] = *(const float4*)(h + (size_t)r[i].y * UNITS + lane * 4);

    // Phase 3: scale
#pragma unroll
    for (int i = 0; i < EPW; i++) {
        const float v = __int_as_float(r[i].z);
        g[i].x *= v; g[i].y *= v; g[i].z *= v; g[i].w *= v;
    }

    // Phase 4: merge runs; atomic flush only at dst boundaries
    float4 acc = g[0];
    int cur = r[0].x;
#pragma unroll
    for (int i = 1; i < EPW; i++) {
        if (r[i].x != cur) {
            atomicAdd((float4*)(out + (size_t)cur * UNITS + lane * 4), acc);
            acc = g[i];
            cur = r[i].x;
        } else {
            acc.x += g[i].x; acc.y += g[i].y; acc.z += g[i].z; acc.w += g[i].w;
        }
    }
    atomicAdd((float4*)(out + (size_t)cur * UNITS + lane * 4), acc);
}

// ============================================================================
// Launch
// ============================================================================
extern "C" void kernel_launch(void* const* d_in, const int* in_sizes, int n_in,
                              void* d_out, int out_size) {
    const float* x    = (const float*)d_in[0];
    const float* w    = (const float*)d_in[1];
    const int*   src  = (const int*)d_in[2];
    const int*   dst  = (const int*)d_in[3];
    const float* vals = (const float*)d_in[4];
    float* out = (float*)d_out;

    cudaMemsetAsync(d_out, 0, (size_t)out_size * sizeof(float), 0);

    float* h;
    cudaGetSymbolAddress((void**)&h, g_h);
    int* countp;
    cudaGetSymbolAddress((void**)&countp, g_count);
    cudaMemsetAsync(countp, 0, N_NODES * sizeof(int), 0);

    // CSR-by-dst build
    hist_kernel<<<(N_EDGES + 255) / 256, 256>>>(dst);
    scan_kernel<<<1, 1024>>>();
    bin_kernel<<<(N_EDGES + 255) / 256, 256>>>(src, dst, vals);

    // w split + GEMM
    split_w_kernel<<<(D_FEAT * UNITS + 255) / 256, 256>>>(w);
    cudaFuncSetAttribute(gemm_mma_kernel,
                         cudaFuncAttributeMaxDynamicSharedMemorySize, SMEM_TOTAL);
    int gemm_blocks = (N_NODES + TILE_M - 1) / TILE_M;
    gemm_mma_kernel<<<gemm_blocks, 256, SMEM_TOTAL>>>(x, h);

    // Balanced segmented aggregate
    int nwarps = (N_EDGES + EPW - 1) / EPW;             // 400000
    int agg_blocks = (nwarps * 32 + 255) / 256;
    aggregate_kernel<<<agg_blocks, 256>>>(h, out);
}

// round 14
// speedup vs baseline: 1.3948x; 1.3011x over previous
#include <cuda_runtime.h>
#include <cuda_bf16.h>
#include <cstdint>

// Problem constants
#define N_NODES 100000
#define N_EDGES 1600000
#define D_FEAT  256
#define UNITS   128

// Static scratch
__device__ float g_h[(size_t)N_NODES * UNITS];                    // 51.2 MB
__device__ __nv_bfloat16 g_wh[UNITS * D_FEAT];                    // w hi, [n][k]
__device__ __nv_bfloat16 g_wl[UNITS * D_FEAT];                    // w lo, [n][k]
__device__ int g_count[N_NODES];
__device__ int g_cursor[N_NODES];
__device__ int4 g_erec[N_EDGES];                                  // {dst, src, val, pad}

// ============================================================================
// Helpers
// ============================================================================
__device__ __forceinline__ uint32_t smem_u32(const void* p) {
    uint32_t a;
    asm("{ .reg .u64 t; cvta.to.shared.u64 t, %1; cvt.u32.u64 %0, t; }"
        : "=r"(a) : "l"(p));
    return a;
}

__device__ __forceinline__ uint32_t pk2(__nv_bfloat16 a, __nv_bfloat16 b) {
    uint16_t ua = *reinterpret_cast<uint16_t*>(&a);
    uint16_t ub = *reinterpret_cast<uint16_t*>(&b);
    return (uint32_t)ua | ((uint32_t)ub << 16);
}

#define LDSM_X4(r0, r1, r2, r3, addr) \
    asm volatile("ldmatrix.sync.aligned.m8n8.x4.shared.b16 {%0,%1,%2,%3}, [%4];" \
        : "=r"(r0), "=r"(r1), "=r"(r2), "=r"(r3) : "r"(addr))

#define MMA_BF16(c, a, b0, b1) \
    asm volatile("mma.sync.aligned.m16n8k16.row.col.f32.bf16.bf16.f32 " \
        "{%0,%1,%2,%3}, {%4,%5,%6,%7}, {%8,%9}, {%0,%1,%2,%3};" \
        : "+f"((c)[0]), "+f"((c)[1]), "+f"((c)[2]), "+f"((c)[3]) \
        : "r"((a)[0]), "r"((a)[1]), "r"((a)[2]), "r"((a)[3]), "r"(b0), "r"(b1))

// ============================================================================
// split_w
// ============================================================================
__global__ __launch_bounds__(256) void split_w_kernel(const float* __restrict__ w) {
    int idx = blockIdx.x * blockDim.x + threadIdx.x;
    if (idx >= D_FEAT * UNITS) return;
    int k = idx >> 7, n = idx & 127;
    float v = w[idx];
    __nv_bfloat16 hi = __float2bfloat16(v);
    __nv_bfloat16 lo = __float2bfloat16(v - __bfloat162float(hi));
    g_wh[n * D_FEAT + k] = hi;
    g_wl[n * D_FEAT + k] = lo;
}

// ============================================================================
// GEMM (unchanged from R10): 2-way bf16 split on mma.sync, 48KB smem.
// ============================================================================
#define TILE_M  128
#define NCHUNK  16
#define PITCH   48
#define BUF_SZ  (128 * PITCH)
#define SMEM_A  0
#define SMEM_B  24576
#define SMEM_TOTAL 49152

__device__ __forceinline__ void cvt_store8(char* smem, int buf, int r, int kq,
                                           float4 v0, float4 v1) {
    float f[8] = {v0.x, v0.y, v0.z, v0.w, v1.x, v1.y, v1.z, v1.w};
    __nv_bfloat16 hi[8], lo[8];
#pragma unroll
    for (int e = 0; e < 8; e++) {
        hi[e] = __float2bfloat16(f[e]);
        lo[e] = __float2bfloat16(f[e] - __bfloat162float(hi[e]));
    }
    char* ph = smem + SMEM_A + buf * (2 * BUF_SZ) + r * PITCH + kq * 2;
    char* pl = ph + BUF_SZ;
    *(uint2*)(ph)     = make_uint2(pk2(hi[0], hi[1]), pk2(hi[2], hi[3]));
    *(uint2*)(ph + 8) = make_uint2(pk2(hi[4], hi[5]), pk2(hi[6], hi[7]));
    *(uint2*)(pl)     = make_uint2(pk2(lo[0], lo[1]), pk2(lo[2], lo[3]));
    *(uint2*)(pl + 8) = make_uint2(pk2(lo[4], lo[5]), pk2(lo[6], lo[7]));
}

__device__ __forceinline__ void b_store(char* smem, int buf, int n, int kq,
                                        uint4 bh, uint4 bl) {
    char* ph = smem + SMEM_B + buf * (2 * BUF_SZ) + n * PITCH + kq * 2;
    *(uint4*)(ph)          = bh;
    *(uint4*)(ph + BUF_SZ) = bl;
}

__global__ __launch_bounds__(256) void gemm_mma_kernel(const float* __restrict__ x,
                                                       float* __restrict__ h) {
    extern __shared__ char smem[];
    const uint32_t sb = smem_u32(smem);
    const int tid  = threadIdx.x;
    const int wid  = tid >> 5;
    const int lane = tid & 31;
    const int block_row = blockIdx.x * TILE_M;

    const int wm = (wid & 3) * 32;
    const int wn = (wid >> 2) * 64;

    const int pr = tid >> 1;
    const int pk = (tid & 1) * 8;
    const int grow = block_row + pr;
    const bool prow_ok = grow < N_NODES;
    const float* xrow = x + (size_t)(prow_ok ? grow : 0) * D_FEAT;
    const __nv_bfloat16* whrow = g_wh + pr * D_FEAT + pk;
    const __nv_bfloat16* wlrow = g_wl + pr * D_FEAT + pk;

    {
        float4 v0 = make_float4(0, 0, 0, 0), v1 = v0;
        if (prow_ok) {
            v0 = *(const float4*)(xrow + pk);
            v1 = *(const float4*)(xrow + pk + 4);
        }
        cvt_store8(smem, 0, pr, pk, v0, v1);
        uint4 bh = *(const uint4*)(whrow);
        uint4 bl = *(const uint4*)(wlrow);
        b_store(smem, 0, pr, pk, bh, bl);
    }
    __syncthreads();

    float acc[2][8][4];
#pragma unroll
    for (int i = 0; i < 2; i++)
#pragma unroll
        for (int j = 0; j < 8; j++)
#pragma unroll
            for (int q = 0; q < 4; q++) acc[i][j][q] = 0.0f;

    const uint32_t aRow = (uint32_t)(wm + (lane & 15)) * PITCH + ((lane >> 4) << 4);
    const uint32_t bRow = (uint32_t)(wn + (lane & 7) + ((lane >> 4) << 3)) * PITCH
                          + (((lane >> 3) & 1) << 4);

    for (int c = 0; c < NCHUNK; c++) {
        float4 v0 = make_float4(0, 0, 0, 0), v1 = v0;
        uint4 nbh = make_uint4(0, 0, 0, 0), nbl = nbh;
        const bool pf = (c + 1 < NCHUNK);
        if (pf) {
            if (prow_ok) {
                v0 = *(const float4*)(xrow + (c + 1) * 16 + pk);
                v1 = *(const float4*)(xrow + (c + 1) * 16 + pk + 4);
            }
            nbh = *(const uint4*)(whrow + (c + 1) * 16);
            nbl = *(const uint4*)(wlrow + (c + 1) * 16);
        }

        const uint32_t abase = sb + SMEM_A + (c & 1) * (2 * BUF_SZ) + aRow;
        uint32_t ah[2][4], al[2][4];
#pragma unroll
        for (int i = 0; i < 2; i++) {
            LDSM_X4(ah[i][0], ah[i][1], ah[i][2], ah[i][3], abase + i * 16 * PITCH);
            LDSM_X4(al[i][0], al[i][1], al[i][2], al[i][3],
                    abase + i * 16 * PITCH + BUF_SZ);
        }

        const uint32_t bbH = sb + SMEM_B + (c & 1) * (2 * BUF_SZ) + bRow;
        const uint32_t bbL = bbH + BUF_SZ;
#pragma unroll
        for (int jp = 0; jp < 4; jp++) {
            uint32_t bh[4], bl[4];
            LDSM_X4(bh[0], bh[1], bh[2], bh[3], bbH + jp * 16 * PITCH);
            LDSM_X4(bl[0], bl[1], bl[2], bl[3], bbL + jp * 16 * PITCH);
#pragma unroll
            for (int i = 0; i < 2; i++) {
                MMA_BF16(acc[i][2 * jp],     ah[i], bh[0], bh[1]);
                MMA_BF16(acc[i][2 * jp + 1], ah[i], bh[2], bh[3]);
                MMA_BF16(acc[i][2 * jp],     ah[i], bl[0], bl[1]);
                MMA_BF16(acc[i][2 * jp + 1], ah[i], bl[2], bl[3]);
                MMA_BF16(acc[i][2 * jp],     al[i], bh[0], bh[1]);
                MMA_BF16(acc[i][2 * jp + 1], al[i], bh[2], bh[3]);
            }
        }

        if (pf) {
            cvt_store8(smem, (c + 1) & 1, pr, pk, v0, v1);
            b_store(smem, (c + 1) & 1, pr, pk, nbh, nbl);
        }
        __syncthreads();
    }

#pragma unroll
    for (int i = 0; i < 2; i++) {
#pragma unroll
        for (int j = 0; j < 8; j++) {
            int row0 = block_row + wm + i * 16 + (lane >> 2);
            int col  = wn + j * 8 + (lane & 3) * 2;
            if (row0 < N_NODES)
                *(float2*)(h + (size_t)row0 * UNITS + col) =
                    make_float2(acc[i][j][0], acc[i][j][1]);
            int row1 = row0 + 8;
            if (row1 < N_NODES)
                *(float2*)(h + (size_t)row1 * UNITS + col) =
                    make_float2(acc[i][j][2], acc[i][j][3]);
        }
    }
}

// ============================================================================
// CSR-by-dst build: histogram -> scan -> bin (16B records)
// ============================================================================
__global__ __launch_bounds__(256) void hist_kernel(const int* __restrict__ dst) {
    int i = blockIdx.x * blockDim.x + threadIdx.x;
    if (i < N_EDGES) atomicAdd(&g_count[dst[i]], 1);
}

__global__ __launch_bounds__(1024) void scan_kernel() {
    __shared__ int part[1024];
    const int tid = threadIdx.x;
    const int CHUNK = (N_NODES + 1023) / 1024;   // 98
    int begin = tid * CHUNK;
    int end = begin + CHUNK;
    if (end > N_NODES) end = N_NODES;
    if (begin > N_NODES) begin = N_NODES;

    int s = 0;
    for (int i = begin; i < end; i++) s += g_count[i];
    part[tid] = s;
    __syncthreads();

    for (int off = 1; off < 1024; off <<= 1) {
        int v = (tid >= off) ? part[tid - off] : 0;
        __syncthreads();
        part[tid] += v;
        __syncthreads();
    }

    int run = (tid == 0) ? 0 : part[tid - 1];
    for (int i = begin; i < end; i++) {
        g_cursor[i] = run;
        run += g_count[i];
    }
}

__global__ __launch_bounds__(256) void bin_kernel(const int* __restrict__ src,
                                                  const int* __restrict__ dst,
                                                  const float* __restrict__ vals) {
    int i = blockIdx.x * blockDim.x + threadIdx.x;
    if (i >= N_EDGES) return;
    int d = dst[i];
    int pos = atomicAdd(&g_cursor[d], 1);
    g_erec[pos] = make_int4(d, src[i], __float_as_int(vals[i]), 0);
}

// ============================================================================
// Aggregate: flat segmented reduction, strict phase separation.
// EPW=8, no occupancy clamp (~80 regs -> 3 CTAs/SM). 200K warps.
// ============================================================================
#define EPW 8

__global__ __launch_bounds__(256) void aggregate_kernel(const float* __restrict__ h,
                                                        float* __restrict__ out) {
    const int warp = (blockIdx.x * blockDim.x + threadIdx.x) >> 5;
    const int lane = threadIdx.x & 31;
    const int base = warp * EPW;
    if (base >= N_EDGES) return;

    const int4* ep = g_erec + base;

    // Phase 1: edge records (broadcast loads, independent)
    int4 r[EPW];
#pragma unroll
    for (int i = 0; i < EPW; i++) r[i] = __ldg(ep + i);

    // Phase 2: all gathers back-to-back (independent -> full MLP)
    float4 g[EPW];
#pragma unroll
    for (int i = 0; i < EPW; i++)
        g[i] = *(const float4*)(h + (size_t)r[i].y * UNITS + lane * 4);

    // Phase 3: scale (register-only)
#pragma unroll
    for (int i = 0; i < EPW; i++) {
        const float v = __int_as_float(r[i].z);
        g[i].x *= v; g[i].y *= v; g[i].z *= v; g[i].w *= v;
    }

    // Phase 4: merge runs; atomic flush only at dst boundaries
    float4 acc = g[0];
    int cur = r[0].x;
#pragma unroll
    for (int i = 1; i < EPW; i++) {
        if (r[i].x != cur) {
            atomicAdd((float4*)(out + (size_t)cur * UNITS + lane * 4), acc);
            acc = g[i];
            cur = r[i].x;
        } else {
            acc.x += g[i].x; acc.y += g[i].y; acc.z += g[i].z; acc.w += g[i].w;
        }
    }
    atomicAdd((float4*)(out + (size_t)cur * UNITS + lane * 4), acc);
}

// ============================================================================
// Launch: graph with parallel branches
//   main:  memsets -> fork -> split_w -> GEMM -> join -> aggregate
//   build:            fork -> hist -> scan -> bin -> join
// Stream/events created once on the first (uncaptured correctness) call;
// capture calls only record/wait, which are graph-capturable.
// ============================================================================
extern "C" void kernel_launch(void* const* d_in, const int* in_sizes, int n_in,
                              void* d_out, int out_size) {
    const float* x    = (const float*)d_in[0];
    const float* w    = (const float*)d_in[1];
    const int*   src  = (const int*)d_in[2];
    const int*   dst  = (const int*)d_in[3];
    const float* vals = (const float*)d_in[4];
    float* out = (float*)d_out;

    static cudaStream_t s_build = nullptr;
    static cudaEvent_t ev_fork = nullptr, ev_join = nullptr;
    if (s_build == nullptr) {
        cudaStreamCreateWithFlags(&s_build, cudaStreamNonBlocking);
        cudaEventCreateWithFlags(&ev_fork, cudaEventDisableTiming);
        cudaEventCreateWithFlags(&ev_join, cudaEventDisableTiming);
    }

    float* h;
    cudaGetSymbolAddress((void**)&h, g_h);
    int* countp;
    cudaGetSymbolAddress((void**)&countp, g_count);

    // Main stream: zero out + histogram
    cudaMemsetAsync(d_out, 0, (size_t)out_size * sizeof(float), 0);
    cudaMemsetAsync(countp, 0, N_NODES * sizeof(int), 0);

    // Fork build branch
    cudaEventRecord(ev_fork, 0);
    cudaStreamWaitEvent(s_build, ev_fork, 0);

    // Build branch (independent of GEMM)
    hist_kernel<<<(N_EDGES + 255) / 256, 256, 0, s_build>>>(dst);
    scan_kernel<<<1, 1024, 0, s_build>>>();
    bin_kernel<<<(N_EDGES + 255) / 256, 256, 0, s_build>>>(src, dst, vals);
    cudaEventRecord(ev_join, s_build);

    // Main branch: w split + GEMM (concurrent with build)
    split_w_kernel<<<(D_FEAT * UNITS + 255) / 256, 256>>>(w);
    cudaFuncSetAttribute(gemm_mma_kernel,
                         cudaFuncAttributeMaxDynamicSharedMemorySize, SMEM_TOTAL);
    int gemm_blocks = (N_NODES + TILE_M - 1) / TILE_M;
    gemm_mma_kernel<<<gemm_blocks, 256, SMEM_TOTAL>>>(x, h);

    // Join, then aggregate
    cudaStreamWaitEvent(0, ev_join, 0);
    int nwarps = (N_EDGES + EPW - 1) / EPW;             // 200000
    int agg_blocks = (nwarps * 32 + 255) / 256;
    aggregate_kernel<<<agg_blocks, 256>>>(h, out);
}

// round 16
// speedup vs baseline: 1.4784x; 1.0599x over previous
#include <cuda_runtime.h>
#include <cuda_bf16.h>
#include <cstdint>

// Problem constants
#define N_NODES 100000
#define N_EDGES 1600000
#define D_FEAT  256
#define UNITS   128

// Static scratch
__device__ float g_h[(size_t)N_NODES * UNITS];                    // 51.2 MB
__device__ __nv_bfloat16 g_wh[UNITS * D_FEAT];                    // w hi, [n][k]
__device__ __nv_bfloat16 g_wl[UNITS * D_FEAT];                    // w lo, [n][k]
__device__ int g_count[N_NODES];
__device__ int g_cursor[N_NODES];
__device__ int4 g_erec[N_EDGES];                                  // {dst, src, val, pad}

// ============================================================================
// Helpers
// ============================================================================
__device__ __forceinline__ uint32_t smem_u32(const void* p) {
    uint32_t a;
    asm("{ .reg .u64 t; cvta.to.shared.u64 t, %1; cvt.u32.u64 %0, t; }"
        : "=r"(a) : "l"(p));
    return a;
}

__device__ __forceinline__ uint32_t pk2(__nv_bfloat16 a, __nv_bfloat16 b) {
    uint16_t ua = *reinterpret_cast<uint16_t*>(&a);
    uint16_t ub = *reinterpret_cast<uint16_t*>(&b);
    return (uint32_t)ua | ((uint32_t)ub << 16);
}

#define LDSM_X4(r0, r1, r2, r3, addr) \
    asm volatile("ldmatrix.sync.aligned.m8n8.x4.shared.b16 {%0,%1,%2,%3}, [%4];" \
        : "=r"(r0), "=r"(r1), "=r"(r2), "=r"(r3) : "r"(addr))

#define MMA_BF16(c, a, b0, b1) \
    asm volatile("mma.sync.aligned.m16n8k16.row.col.f32.bf16.bf16.f32 " \
        "{%0,%1,%2,%3}, {%4,%5,%6,%7}, {%8,%9}, {%0,%1,%2,%3};" \
        : "+f"((c)[0]), "+f"((c)[1]), "+f"((c)[2]), "+f"((c)[3]) \
        : "r"((a)[0]), "r"((a)[1]), "r"((a)[2]), "r"((a)[3]), "r"(b0), "r"(b1))

// ============================================================================
// split_w
// ============================================================================
__global__ __launch_bounds__(256) void split_w_kernel(const float* __restrict__ w) {
    int idx = blockIdx.x * blockDim.x + threadIdx.x;
    if (idx >= D_FEAT * UNITS) return;
    int k = idx >> 7, n = idx & 127;
    float v = w[idx];
    __nv_bfloat16 hi = __float2bfloat16(v);
    __nv_bfloat16 lo = __float2bfloat16(v - __bfloat162float(hi));
    g_wh[n * D_FEAT + k] = hi;
    g_wl[n * D_FEAT + k] = lo;
}

// ============================================================================
// GEMM (unchanged from R10): 2-way bf16 split on mma.sync, 48KB smem.
// ============================================================================
#define TILE_M  128
#define NCHUNK  16
#define PITCH   48
#define BUF_SZ  (128 * PITCH)
#define SMEM_A  0
#define SMEM_B  24576
#define SMEM_TOTAL 49152

__device__ __forceinline__ void cvt_store8(char* smem, int buf, int r, int kq,
                                           float4 v0, float4 v1) {
    float f[8] = {v0.x, v0.y, v0.z, v0.w, v1.x, v1.y, v1.z, v1.w};
    __nv_bfloat16 hi[8], lo[8];
#pragma unroll
    for (int e = 0; e < 8; e++) {
        hi[e] = __float2bfloat16(f[e]);
        lo[e] = __float2bfloat16(f[e] - __bfloat162float(hi[e]));
    }
    char* ph = smem + SMEM_A + buf * (2 * BUF_SZ) + r * PITCH + kq * 2;
    char* pl = ph + BUF_SZ;
    *(uint2*)(ph)     = make_uint2(pk2(hi[0], hi[1]), pk2(hi[2], hi[3]));
    *(uint2*)(ph + 8) = make_uint2(pk2(hi[4], hi[5]), pk2(hi[6], hi[7]));
    *(uint2*)(pl)     = make_uint2(pk2(lo[0], lo[1]), pk2(lo[2], lo[3]));
    *(uint2*)(pl + 8) = make_uint2(pk2(lo[4], lo[5]), pk2(lo[6], lo[7]));
}

__device__ __forceinline__ void b_store(char* smem, int buf, int n, int kq,
                                        uint4 bh, uint4 bl) {
    char* ph = smem + SMEM_B + buf * (2 * BUF_SZ) + n * PITCH + kq * 2;
    *(uint4*)(ph)          = bh;
    *(uint4*)(ph + BUF_SZ) = bl;
}

__global__ __launch_bounds__(256) void gemm_mma_kernel(const float* __restrict__ x,
                                                       float* __restrict__ h) {
    extern __shared__ char smem[];
    const uint32_t sb = smem_u32(smem);
    const int tid  = threadIdx.x;
    const int wid  = tid >> 5;
    const int lane = tid & 31;
    const int block_row = blockIdx.x * TILE_M;

    const int wm = (wid & 3) * 32;
    const int wn = (wid >> 2) * 64;

    const int pr = tid >> 1;
    const int pk = (tid & 1) * 8;
    const int grow = block_row + pr;
    const bool prow_ok = grow < N_NODES;
    const float* xrow = x + (size_t)(prow_ok ? grow : 0) * D_FEAT;
    const __nv_bfloat16* whrow = g_wh + pr * D_FEAT + pk;
    const __nv_bfloat16* wlrow = g_wl + pr * D_FEAT + pk;

    {
        float4 v0 = make_float4(0, 0, 0, 0), v1 = v0;
        if (prow_ok) {
            v0 = *(const float4*)(xrow + pk);
            v1 = *(const float4*)(xrow + pk + 4);
        }
        cvt_store8(smem, 0, pr, pk, v0, v1);
        uint4 bh = *(const uint4*)(whrow);
        uint4 bl = *(const uint4*)(wlrow);
        b_store(smem, 0, pr, pk, bh, bl);
    }
    __syncthreads();

    float acc[2][8][4];
#pragma unroll
    for (int i = 0; i < 2; i++)
#pragma unroll
        for (int j = 0; j < 8; j++)
#pragma unroll
            for (int q = 0; q < 4; q++) acc[i][j][q] = 0.0f;

    const uint32_t aRow = (uint32_t)(wm + (lane & 15)) * PITCH + ((lane >> 4) << 4);
    const uint32_t bRow = (uint32_t)(wn + (lane & 7) + ((lane >> 4) << 3)) * PITCH
                          + (((lane >> 3) & 1) << 4);

    for (int c = 0; c < NCHUNK; c++) {
        float4 v0 = make_float4(0, 0, 0, 0), v1 = v0;
        uint4 nbh = make_uint4(0, 0, 0, 0), nbl = nbh;
        const bool pf = (c + 1 < NCHUNK);
        if (pf) {
            if (prow_ok) {
                v0 = *(const float4*)(xrow + (c + 1) * 16 + pk);
                v1 = *(const float4*)(xrow + (c + 1) * 16 + pk + 4);
            }
            nbh = *(const uint4*)(whrow + (c + 1) * 16);
            nbl = *(const uint4*)(wlrow + (c + 1) * 16);
        }

        const uint32_t abase = sb + SMEM_A + (c & 1) * (2 * BUF_SZ) + aRow;
        uint32_t ah[2][4], al[2][4];
#pragma unroll
        for (int i = 0; i < 2; i++) {
            LDSM_X4(ah[i][0], ah[i][1], ah[i][2], ah[i][3], abase + i * 16 * PITCH);
            LDSM_X4(al[i][0], al[i][1], al[i][2], al[i][3],
                    abase + i * 16 * PITCH + BUF_SZ);
        }

        const uint32_t bbH = sb + SMEM_B + (c & 1) * (2 * BUF_SZ) + bRow;
        const uint32_t bbL = bbH + BUF_SZ;
#pragma unroll
        for (int jp = 0; jp < 4; jp++) {
            uint32_t bh[4], bl[4];
            LDSM_X4(bh[0], bh[1], bh[2], bh[3], bbH + jp * 16 * PITCH);
            LDSM_X4(bl[0], bl[1], bl[2], bl[3], bbL + jp * 16 * PITCH);
#pragma unroll
            for (int i = 0; i < 2; i++) {
                MMA_BF16(acc[i][2 * jp],     ah[i], bh[0], bh[1]);
                MMA_BF16(acc[i][2 * jp + 1], ah[i], bh[2], bh[3]);
                MMA_BF16(acc[i][2 * jp],     ah[i], bl[0], bl[1]);
                MMA_BF16(acc[i][2 * jp + 1], ah[i], bl[2], bl[3]);
                MMA_BF16(acc[i][2 * jp],     al[i], bh[0], bh[1]);
                MMA_BF16(acc[i][2 * jp + 1], al[i], bh[2], bh[3]);
            }
        }

        if (pf) {
            cvt_store8(smem, (c + 1) & 1, pr, pk, v0, v1);
            b_store(smem, (c + 1) & 1, pr, pk, nbh, nbl);
        }
        __syncthreads();
    }

#pragma unroll
    for (int i = 0; i < 2; i++) {
#pragma unroll
        for (int j = 0; j < 8; j++) {
            int row0 = block_row + wm + i * 16 + (lane >> 2);
            int col  = wn + j * 8 + (lane & 3) * 2;
            if (row0 < N_NODES)
                *(float2*)(h + (size_t)row0 * UNITS + col) =
                    make_float2(acc[i][j][0], acc[i][j][1]);
            int row1 = row0 + 8;
            if (row1 < N_NODES)
                *(float2*)(h + (size_t)row1 * UNITS + col) =
                    make_float2(acc[i][j][2], acc[i][j][3]);
        }
    }
}

// ============================================================================
// CSR-by-dst build: histogram -> scan -> bin (16B records)
// ============================================================================
__global__ __launch_bounds__(256) void hist_kernel(const int* __restrict__ dst) {
    int i = blockIdx.x * blockDim.x + threadIdx.x;
    if (i < N_EDGES) atomicAdd(&g_count[dst[i]], 1);
}

__global__ __launch_bounds__(1024) void scan_kernel() {
    __shared__ int part[1024];
    const int tid = threadIdx.x;
    const int CHUNK = (N_NODES + 1023) / 1024;   // 98
    int begin = tid * CHUNK;
    int end = begin + CHUNK;
    if (end > N_NODES) end = N_NODES;
    if (begin > N_NODES) begin = N_NODES;

    int s = 0;
    for (int i = begin; i < end; i++) s += g_count[i];
    part[tid] = s;
    __syncthreads();

    for (int off = 1; off < 1024; off <<= 1) {
        int v = (tid >= off) ? part[tid - off] : 0;
        __syncthreads();
        part[tid] += v;
        __syncthreads();
    }

    int run = (tid == 0) ? 0 : part[tid - 1];
    for (int i = begin; i < end; i++) {
        g_cursor[i] = run;
        run += g_count[i];
    }
}

__global__ __launch_bounds__(256) void bin_kernel(const int* __restrict__ src,
                                                  const int* __restrict__ dst,
                                                  const float* __restrict__ vals) {
    int i = blockIdx.x * blockDim.x + threadIdx.x;
    if (i >= N_EDGES) return;
    int d = dst[i];
    int pos = atomicAdd(&g_cursor[d], 1);
    g_erec[pos] = make_int4(d, src[i], __float_as_int(vals[i]), 0);
}

// ============================================================================
// Aggregate: segmented reduction, records staged through SMEM to cut regs.
// Block = 8 warps x EPW=8 edges = 64 records (1KB smem). 25000 blocks exact.
// __launch_bounds__(256,4): <=64 regs -> 4 CTAs/SM (50% occ), 8-deep MLP.
// ============================================================================
#define EPW 8
#define RECS 64   // records per block = (256/32) * EPW

__global__ __launch_bounds__(256, 4) void aggregate_kernel(const float* __restrict__ h,
                                                           float* __restrict__ out) {
    __shared__ int4 srec[RECS];
    const int tid = threadIdx.x;

    // Cooperative coalesced staging: 64 int4 = 256 b32 words, one per thread.
    ((int*)srec)[tid] =
        ((const int*)g_erec)[(size_t)blockIdx.x * (RECS * 4) + tid];
    __syncthreads();

    const int wid  = tid >> 5;
    const int lane = tid & 31;
    const int4* my = srec + wid * EPW;

    // Phase 1: all gathers back-to-back (src read from smem; full MLP)
    float4 g[EPW];
#pragma unroll
    for (int i = 0; i < EPW; i++) {
        const int s = my[i].y;
        g[i] = *(const float4*)(h + (size_t)s * UNITS + lane * 4);
    }

    // Phase 2: scale by edge value (val re-read from smem broadcast)
#pragma unroll
    for (int i = 0; i < EPW; i++) {
        const float v = __int_as_float(my[i].z);
        g[i].x *= v; g[i].y *= v; g[i].z *= v; g[i].w *= v;
    }

    // Phase 3: merge runs of equal dst; atomic flush at boundaries only
    float4 acc = g[0];
    int cur = my[0].x;
#pragma unroll
    for (int i = 1; i < EPW; i++) {
        const int d = my[i].x;
        if (d != cur) {
            atomicAdd((float4*)(out + (size_t)cur * UNITS + lane * 4), acc);
            acc = g[i];
            cur = d;
        } else {
            acc.x += g[i].x; acc.y += g[i].y; acc.z += g[i].z; acc.w += g[i].w;
        }
    }
    atomicAdd((float4*)(out + (size_t)cur * UNITS + lane * 4), acc);
}

// ============================================================================
// Launch: graph with parallel branches
//   main:  memset(count) -> fork -> memset(out) -> split_w -> GEMM -> join -> agg
//   build:                  fork -> hist -> scan -> bin -> join
// ============================================================================
extern "C" void kernel_launch(void* const* d_in, const int* in_sizes, int n_in,
                              void* d_out, int out_size) {
    const float* x    = (const float*)d_in[0];
    const float* w    = (const float*)d_in[1];
    const int*   src  = (const int*)d_in[2];
    const int*   dst  = (const int*)d_in[3];
    const float* vals = (const float*)d_in[4];
    float* out = (float*)d_out;

    static cudaStream_t s_build = nullptr;
    static cudaEvent_t ev_fork = nullptr, ev_join = nullptr;
    if (s_build == nullptr) {
        cudaStreamCreateWithFlags(&s_build, cudaStreamNonBlocking);
        cudaEventCreateWithFlags(&ev_fork, cudaEventDisableTiming);
        cudaEventCreateWithFlags(&ev_join, cudaEventDisableTiming);
    }

    float* h;
    cudaGetSymbolAddress((void**)&h, g_h);
    int* countp;
    cudaGetSymbolAddress((void**)&countp, g_count);

    // Histogram zero first, so the build branch can fork immediately.
    cudaMemsetAsync(countp, 0, N_NODES * sizeof(int), 0);

    // Fork build branch
    cudaEventRecord(ev_fork, 0);
    cudaStreamWaitEvent(s_build, ev_fork, 0);

    // Build branch (independent of GEMM)
    hist_kernel<<<(N_EDGES + 255) / 256, 256, 0, s_build>>>(dst);
    scan_kernel<<<1, 1024, 0, s_build>>>();
    bin_kernel<<<(N_EDGES + 255) / 256, 256, 0, s_build>>>(src, dst, vals);
    cudaEventRecord(ev_join, s_build);

    // Main branch: out zero + w split + GEMM (concurrent with build)
    cudaMemsetAsync(d_out, 0, (size_t)out_size * sizeof(float), 0);
    split_w_kernel<<<(D_FEAT * UNITS + 255) / 256, 256>>>(w);
    cudaFuncSetAttribute(gemm_mma_kernel,
                         cudaFuncAttributeMaxDynamicSharedMemorySize, SMEM_TOTAL);
    int gemm_blocks = (N_NODES + TILE_M - 1) / TILE_M;
    gemm_mma_kernel<<<gemm_blocks, 256, SMEM_TOTAL>>>(x, h);

    // Join, then aggregate
    cudaStreamWaitEvent(0, ev_join, 0);
    aggregate_kernel<<<N_EDGES / RECS, 256>>>(h, out);   // 25000 blocks
}